// round 15
// baseline (speedup 1.0000x reference)
#include <cuda_runtime.h>
#include <cuda_fp16.h>
#include <cstdint>

// NearestEmbed: x (64,64,32,32) f32, emb (64,512) f32
// out f32 = [ quantized 4194304 | argmin 65536 (as float) ]
//
// R15: three kernels.
//  prep:   build HMMA B-fragments + norms ONCE into __device__ globals.
//  main:   256 thr, launch_bounds(256,3) -> 24 warps/SM (reg cap 80, loop kept
//          lean: R6 branchy top-2, unroll 2, one A-tile). smem = frag copy
//          (66KB) only. Emits indices.
//  gather: R11's smem-staged code gather (measured 8.8us).

#define EMB_D 64
#define EMB_K 512
#define HW 1024
#define MARGIN 0.04f

__device__ uint32_t g_frags[16384];   // 64KB
__device__ float    g_norms[512];

__device__ __forceinline__ uint32_t packh2(float a, float b) {
    __half2 h = __floats2half2_rn(a, b);
    return *reinterpret_cast<uint32_t*>(&h);
}

__device__ __forceinline__ void hmma16816(float& c0, float& c1, float& c2, float& c3,
                                          uint32_t a0, uint32_t a1, uint32_t a2, uint32_t a3,
                                          uint32_t b0, uint32_t b1) {
    asm volatile("mma.sync.aligned.m16n8k16.row.col.f32.f16.f16.f32 "
                 "{%0,%1,%2,%3}, {%4,%5,%6,%7}, {%8,%9}, {%0,%1,%2,%3};"
                 : "+f"(c0), "+f"(c1), "+f"(c2), "+f"(c3)
                 : "r"(a0), "r"(a1), "r"(a2), "r"(a3), "r"(b0), "r"(b1));
}

// ---------------- prep: fragments + norms (once) ----------------
__global__ void vq_prep(const float* __restrict__ emb)
{
    const int tid = threadIdx.x;
    const int bid = blockIdx.x;
    if (bid < 64) {
        int f = bid * 256 + tid;      // 0..16383
        int j  = f & 1;
        int ln = (f >> 1) & 31;
        int ks = (f >> 6) & 3;
        int nt = f >> 8;
        int n  = nt * 8 + (ln >> 2);
        int d0 = ks * 16 + 2 * (ln & 3) + 8 * j;
        g_frags[f] = packh2(__ldg(emb + d0 * EMB_K + n), __ldg(emb + (d0 + 1) * EMB_K + n));
    } else {
        int k = (bid - 64) * 256 + tid;   // 0..511
        float s = 0.f;
        #pragma unroll 8
        for (int d = 0; d < EMB_D; d++) {
            float v = __ldg(emb + d * EMB_K + k);
            s = fmaf(v, v, s);
        }
        g_norms[k] = s;
    }
}

// ---------------- main: coarse HMMA + exact rescue, indices only ----------------
#define MTHREADS 256           // 8 warps, warp owns 16 rows
#define TILE_M 128
#define MGRID 512

// smem (bytes)
#define SM_FRAGS 0                       // 64KB
#define SM_NORMS 65536                   // 2KB
#define SM_WSM   (SM_NORMS + 2048)       // i32 [8][16]
#define SM_XS    (SM_WSM + 512)          // f32 [8][64]
#define SM_TOTAL (SM_XS + 2048)

__global__ __launch_bounds__(MTHREADS, 3)
void vq_main(const float* __restrict__ x,
             const float* __restrict__ emb,
             float* __restrict__ out_idx)
{
    extern __shared__ char smem[];
    uint32_t* frags = reinterpret_cast<uint32_t*>(smem + SM_FRAGS);
    float*    norms = reinterpret_cast<float*>(smem + SM_NORMS);

    const int tid  = threadIdx.x;
    const int warp = tid >> 5;
    const int lane = tid & 31;
    const int gidq = lane & 3;
    const int grp  = lane >> 2;

    int*   wsm = reinterpret_cast<int*>(smem + SM_WSM) + warp * 16;
    float* xs  = reinterpret_cast<float*>(smem + SM_XS) + warp * 64;

    // ---- prologue: coalesced copy of prebuilt fragments + norms ----
    {
        const uint4* gf = reinterpret_cast<const uint4*>(g_frags);
        uint4* sf = reinterpret_cast<uint4*>(frags);
        #pragma unroll
        for (int i = 0; i < 4096 / MTHREADS; i++)
            sf[i * MTHREADS + tid] = gf[i * MTHREADS + tid];
        #pragma unroll
        for (int i = 0; i < EMB_K / MTHREADS; i++)
            norms[i * MTHREADS + tid] = g_norms[i * MTHREADS + tid];
    }
    __syncthreads();   // warps fully independent afterwards

    const int row_base = blockIdx.x * TILE_M;
    const int b = row_base >> 10;
    const int hw_base = row_base & (HW - 1);
    const float* xb = x + (size_t)b * (EMB_D * HW) + hw_base;   // x(row,d)=xb[d*HW+row]
    const int wrow = warp * 16;

    // ---- A fragments: this warp's 16 rows ----
    const float* xw = xb + wrow;
    uint32_t A[4][4];
    {
        const int q2 = gidq * 2;
        #pragma unroll
        for (int ks = 0; ks < 4; ks++) {
            int d = ks * 16 + q2;
            A[ks][0] = packh2(xw[d * HW + grp],           xw[(d + 1) * HW + grp]);
            A[ks][1] = packh2(xw[d * HW + grp + 8],       xw[(d + 1) * HW + grp + 8]);
            A[ks][2] = packh2(xw[(d + 8) * HW + grp],     xw[(d + 9) * HW + grp]);
            A[ks][3] = packh2(xw[(d + 8) * HW + grp + 8], xw[(d + 9) * HW + grp + 8]);
        }
    }

    // ---- coarse scan over 64 n-tiles (R6 loop, unroll 2 for reg safety) ----
    const float INF = __int_as_float(0x7f800000);
    float b1a = INF, b2a = INF, b1b = INF, b2b = INF;
    int k1a = 0, k1b = 0;

    const uint2* fr2 = reinterpret_cast<const uint2*>(frags);
    #pragma unroll 2
    for (int nt = 0; nt < 64; nt++) {
        float c0 = 0.f, c1 = 0.f, c2 = 0.f, c3 = 0.f;
        #pragma unroll
        for (int ks = 0; ks < 4; ks++) {
            uint2 bb = fr2[(nt * 4 + ks) * 32 + lane];
            hmma16816(c0, c1, c2, c3, A[ks][0], A[ks][1], A[ks][2], A[ks][3], bb.x, bb.y);
        }
        const int n0 = nt * 8 + gidq * 2;
        float2 nr = *reinterpret_cast<const float2*>(norms + n0);
        float s0 = fmaf(-2.f, c0, nr.x);
        float s1 = fmaf(-2.f, c1, nr.y);
        float s2 = fmaf(-2.f, c2, nr.x);
        float s3 = fmaf(-2.f, c3, nr.y);
        if (s0 < b1a) { b2a = b1a; b1a = s0; k1a = n0; } else b2a = fminf(b2a, s0);
        if (s1 < b1a) { b2a = b1a; b1a = s1; k1a = n0 + 1; } else b2a = fminf(b2a, s1);
        if (s2 < b1b) { b2b = b1b; b1b = s2; k1b = n0; } else b2b = fminf(b2b, s2);
        if (s3 < b1b) { b2b = b1b; b1b = s3; k1b = n0 + 1; } else b2b = fminf(b2b, s3);
    }

    // ---- merge across the 4 lanes of each row-group ----
    #pragma unroll
    for (int off = 1; off <= 2; off <<= 1) {
        float ob1 = __shfl_xor_sync(0xffffffffu, b1a, off);
        int   ok1 = __shfl_xor_sync(0xffffffffu, k1a, off);
        float ob2 = __shfl_xor_sync(0xffffffffu, b2a, off);
        float nb2 = fminf(fmaxf(b1a, ob1), fminf(b2a, ob2));
        bool take = (ob1 < b1a) || (ob1 == b1a && ok1 < k1a);
        b1a = take ? ob1 : b1a; k1a = take ? ok1 : k1a; b2a = nb2;

        float pb = __shfl_xor_sync(0xffffffffu, b1b, off);
        int   pk = __shfl_xor_sync(0xffffffffu, k1b, off);
        float pq = __shfl_xor_sync(0xffffffffu, b2b, off);
        float qb = fminf(fmaxf(b1b, pb), fminf(b2b, pq));
        bool tk = (pb < b1b) || (pb == b1b && pk < k1b);
        b1b = tk ? pb : b1b; k1b = tk ? pk : k1b; b2b = qb;
    }

    // ---- record winners, mark ambiguous rows (in-warp) ----
    bool own = (gidq == 0);
    if (own) {
        wsm[grp]     = k1a;
        wsm[grp + 8] = k1b;
    }
    uint32_t mA = __ballot_sync(0xffffffffu, own && (b2a - b1a <= MARGIN));
    uint32_t mB = __ballot_sync(0xffffffffu, own && (b2b - b1b <= MARGIN));
    __syncwarp();

    uint32_t amb = 0;
    #pragma unroll
    for (int g = 0; g < 8; g++) {
        amb |= ((mA >> (4 * g)) & 1u) << g;
        amb |= ((mB >> (4 * g)) & 1u) << (g + 8);
    }

    // ---- in-warp exact fp32 rescue for ambiguous rows (rare; emb via L2) ----
    while (amb) {
        int r = __ffs(amb) - 1;
        amb &= amb - 1;
        const float* xg = xb + wrow + r;
        xs[lane]      = xg[(size_t)lane * HW];
        xs[lane + 32] = xg[(size_t)(lane + 32) * HW];
        __syncwarp();
        float best = __int_as_float(0x7f800000);
        int bk = 0;
        #pragma unroll 1
        for (int j = 0; j < 16; j++) {
            int k = lane + 32 * j;
            float acc = 0.f;
            #pragma unroll 8
            for (int d = 0; d < EMB_D; d++)
                acc = fmaf(xs[d], __ldg(emb + d * EMB_K + k), acc);
            float sc = fmaf(-2.f, acc, norms[k]);
            if (sc < best) { best = sc; bk = k; }
        }
        #pragma unroll
        for (int off = 16; off >= 1; off >>= 1) {
            float os = __shfl_xor_sync(0xffffffffu, best, off);
            int   ok = __shfl_xor_sync(0xffffffffu, bk, off);
            bool take = (os < best) || (os == best && ok < bk);
            best = take ? os : best;
            bk = take ? ok : bk;
        }
        if (lane == 0) wsm[r] = bk;
        __syncwarp();
    }
    __syncwarp();

    if (lane < 16) out_idx[row_base + wrow + lane] = (float)wsm[lane];
}

// ---------------- gather: out_q[b][d][hw] = emb[d][k(n)] (R11, 8.8us) ----------------
#define GTHREADS 512
#define GGRID 128
#define GSMEM (EMB_D * EMB_K * 4)        // 128KB

__global__ __launch_bounds__(GTHREADS, 1)
void vq_gather(const float* __restrict__ emb,
               const float* __restrict__ out_idx,
               float* __restrict__ out_q)
{
    extern __shared__ float emb_s[];   // [64][512]
    const int tid = threadIdx.x;
    #pragma unroll
    for (int i = 0; i < EMB_D * EMB_K / GTHREADS; i++)
        emb_s[i * GTHREADS + tid] = emb[i * GTHREADS + tid];
    __syncthreads();

    const int n = blockIdx.x * GTHREADS + tid;
    const int b = n >> 10;
    const int hw = n & (HW - 1);
    const int k = (int)out_idx[n];

    float* oq = out_q + (size_t)b * (EMB_D * HW) + hw;
    #pragma unroll
    for (int d = 0; d < EMB_D; d++)
        oq[(size_t)d * HW] = emb_s[d * EMB_K + k];
}

extern "C" void kernel_launch(void* const* d_in, const int* in_sizes, int n_in,
                              void* d_out, int out_size)
{
    const float* x   = (const float*)d_in[0];   // 4194304 f32
    const float* emb = (const float*)d_in[1];   // 32768 f32
    float* out_q = (float*)d_out;
    float* out_i = (float*)d_out + (size_t)4194304;

    cudaFuncSetAttribute(vq_main,
                         cudaFuncAttributeMaxDynamicSharedMemorySize, SM_TOTAL);
    cudaFuncSetAttribute(vq_gather,
                         cudaFuncAttributeMaxDynamicSharedMemorySize, GSMEM);

    vq_prep<<<66, 256>>>(emb);
    vq_main<<<MGRID, MTHREADS, SM_TOTAL>>>(x, emb, out_i);
    vq_gather<<<GGRID, GTHREADS, GSMEM>>>(emb, out_i, out_q);
}

// round 16
// speedup vs baseline: 2.9804x; 2.9804x over previous
#include <cuda_runtime.h>
#include <cuda_fp16.h>
#include <cstdint>

// NearestEmbed: x (64,64,32,32) f32, emb (64,512) f32
// out f32 = [ quantized 4194304 | argmin 65536 (as float) ]
//
// R16: R8 (best, 53.8us) + three state-neutral cuts:
//  1) A fragments pre-scaled by -2 (exact in fp16)
//  2) HMMA accumulators initialized with norms -> score = accumulator directly
//     (deletes 4 FFMA/nt and one dependency stage)
//  3) branch-free top-2 (R13-verified)

#define THREADS 512            // 16 warps, warp handles 16 rows
#define TILE_M 256             // rows per CTA tile
#define GRID 128
#define TILES_PER_CTA 2        // 256 tiles total / 128 CTAs
#define EMB_D 64
#define EMB_K 512
#define HW 1024
#define MARGIN 0.04f

// smem layout (bytes)
#define SM_FRAGS 0                       // u32 frags[64 nt][4 ks][32 lane][2] = 64KB
#define SM_EMB   65536                   // f32 emb_s[64][512] = 128KB
#define SM_NORMS (SM_EMB + 131072)       // f32 [512] = 2KB
#define SM_WIN   (SM_NORMS + 2048)       // i32 [256]
#define SM_QUEUE (SM_WIN + 1024)         // i32 [256]
#define SM_QCNT  (SM_QUEUE + 1024)       // i32
#define SM_XS    (SM_QCNT + 16)          // f32 [16 warps][64] = 4KB
#define SM_TOTAL (SM_XS + 4096)

__device__ __forceinline__ uint32_t packh2(float a, float b) {
    __half2 h = __floats2half2_rn(a, b);
    return *reinterpret_cast<uint32_t*>(&h);
}

__device__ __forceinline__ void hmma16816(float& c0, float& c1, float& c2, float& c3,
                                          uint32_t a0, uint32_t a1, uint32_t a2, uint32_t a3,
                                          uint32_t b0, uint32_t b1) {
    asm volatile("mma.sync.aligned.m16n8k16.row.col.f32.f16.f16.f32 "
                 "{%0,%1,%2,%3}, {%4,%5,%6,%7}, {%8,%9}, {%0,%1,%2,%3};"
                 : "+f"(c0), "+f"(c1), "+f"(c2), "+f"(c3)
                 : "r"(a0), "r"(a1), "r"(a2), "r"(a3), "r"(b0), "r"(b1));
}

// Branch-free top-2 update with a pair of adjacent-code scores (R13-verified).
__device__ __forceinline__ void top2_pair(float s0, float s1, int n0,
                                          float& b1, float& b2, int& k1) {
    float sm = fminf(s0, s1);
    float pm = fmaxf(s0, s1);
    int  km = n0 + ((s1 < s0) ? 1 : 0);
    bool take = (sm < b1);
    float t1 = take ? b1 : b2;
    float t2 = take ? pm : sm;
    b2 = fminf(t1, fminf(b2, t2));
    b1 = take ? sm : b1;
    k1 = take ? km : k1;
}

__global__ __launch_bounds__(THREADS, 1)
void vq_hmma_kernel(const float* __restrict__ x,
                    const float* __restrict__ emb,
                    float* __restrict__ out_q,
                    float* __restrict__ out_idx)
{
    extern __shared__ char smem[];
    uint32_t* frags   = reinterpret_cast<uint32_t*>(smem + SM_FRAGS);
    float*    emb_s   = reinterpret_cast<float*>(smem + SM_EMB);
    float*    norms   = reinterpret_cast<float*>(smem + SM_NORMS);
    int*      winners = reinterpret_cast<int*>(smem + SM_WIN);
    int*      queue   = reinterpret_cast<int*>(smem + SM_QUEUE);
    int*      qcnt    = reinterpret_cast<int*>(smem + SM_QCNT);
    float*    xscr    = reinterpret_cast<float*>(smem + SM_XS);

    const int tid  = threadIdx.x;
    const int warp = tid >> 5;
    const int lane = tid & 31;
    const int gidq = lane & 3;
    const int grp  = lane >> 2;

    // ---- Prologue (once per CTA) ----
    for (int i = tid; i < EMB_D * EMB_K; i += THREADS) emb_s[i] = emb[i];
    if (tid == 0) *qcnt = 0;
    __syncthreads();

    for (int k = tid; k < EMB_K; k += THREADS) {
        float s = 0.f;
        #pragma unroll
        for (int d = 0; d < EMB_D; d++) {
            float v = emb_s[d * EMB_K + k];
            s = fmaf(v, v, s);
        }
        norms[k] = s;
    }
    // B fragments: frags[((nt*4+ks)*32 + lane)*2 + j]
    for (int f = tid; f < 64 * 4 * 32 * 2; f += THREADS) {
        int j  = f & 1;
        int ln = (f >> 1) & 31;
        int ks = (f >> 6) & 3;
        int nt = f >> 8;
        int n  = nt * 8 + (ln >> 2);
        int d0 = ks * 16 + 2 * (ln & 3) + 8 * j;
        frags[f] = packh2(emb_s[d0 * EMB_K + n], emb_s[(d0 + 1) * EMB_K + n]);
    }
    __syncthreads();

    for (int it = 0; it < TILES_PER_CTA; it++) {
        const int tile = blockIdx.x * TILES_PER_CTA + it;
        const int row_base = tile * TILE_M;
        const int b = row_base >> 10;
        const int hw_base = row_base & (HW - 1);
        const float* xb = x + (size_t)b * (EMB_D * HW) + hw_base;   // x(row,d)=xb[d*HW+row]

        // ---- A fragments: this warp's 16 rows, PRE-SCALED by -2 (exact) ----
        const float* xw = xb + warp * 16;
        uint32_t A[4][4];
        {
            const int q2 = gidq * 2;
            #pragma unroll
            for (int ks = 0; ks < 4; ks++) {
                int d = ks * 16 + q2;
                A[ks][0] = packh2(-2.f * xw[d * HW + grp],           -2.f * xw[(d + 1) * HW + grp]);
                A[ks][1] = packh2(-2.f * xw[d * HW + grp + 8],       -2.f * xw[(d + 1) * HW + grp + 8]);
                A[ks][2] = packh2(-2.f * xw[(d + 8) * HW + grp],     -2.f * xw[(d + 9) * HW + grp]);
                A[ks][3] = packh2(-2.f * xw[(d + 8) * HW + grp + 8], -2.f * xw[(d + 9) * HW + grp + 8]);
            }
        }

        // ---- coarse scan: even/odd split top-2 states (R8), norm-init accum ----
        float b1a[2], b2a[2], b1b[2], b2b[2];
        int   k1a[2], k1b[2];
        #pragma unroll
        for (int p = 0; p < 2; p++) {
            b1a[p] = b2a[p] = b1b[p] = b2b[p] = __int_as_float(0x7f800000);
            k1a[p] = k1b[p] = 0;
        }

        const uint2* fr2 = reinterpret_cast<const uint2*>(frags);
        #pragma unroll 4
        for (int nt = 0; nt < 64; nt++) {
            const int p = nt & 1;
            const int n0 = nt * 8 + gidq * 2;
            float2 nr = *reinterpret_cast<const float2*>(norms + n0);
            // accumulators start at ||e||^2; A holds -2x  =>  c == score after MMAs
            float c0 = nr.x, c1 = nr.y, c2 = nr.x, c3 = nr.y;
            #pragma unroll
            for (int ks = 0; ks < 4; ks++) {
                uint2 bb = fr2[(nt * 4 + ks) * 32 + lane];
                hmma16816(c0, c1, c2, c3, A[ks][0], A[ks][1], A[ks][2], A[ks][3], bb.x, bb.y);
            }
            top2_pair(c0, c1, n0, b1a[p], b2a[p], k1a[p]);
            top2_pair(c2, c3, n0, b1b[p], b2b[p], k1b[p]);
        }

        // merge odd state into even (lowest-index wins ties)
        float b1A, b2A, b1B, b2B; int k1A, k1B;
        {
            bool ta = (b1a[1] < b1a[0]) || (b1a[1] == b1a[0] && k1a[1] < k1a[0]);
            b1A = ta ? b1a[1] : b1a[0];
            k1A = ta ? k1a[1] : k1a[0];
            b2A = fminf(fmaxf(b1a[0], b1a[1]), fminf(b2a[0], b2a[1]));
            bool tb = (b1b[1] < b1b[0]) || (b1b[1] == b1b[0] && k1b[1] < k1b[0]);
            b1B = tb ? b1b[1] : b1b[0];
            k1B = tb ? k1b[1] : k1b[0];
            b2B = fminf(fmaxf(b1b[0], b1b[1]), fminf(b2b[0], b2b[1]));
        }

        // ---- merge across the 4 lanes of each row-group ----
        #pragma unroll
        for (int off = 1; off <= 2; off <<= 1) {
            float ob1 = __shfl_xor_sync(0xffffffffu, b1A, off);
            int   ok1 = __shfl_xor_sync(0xffffffffu, k1A, off);
            float ob2 = __shfl_xor_sync(0xffffffffu, b2A, off);
            float nb2 = fminf(fmaxf(b1A, ob1), fminf(b2A, ob2));
            bool take = (ob1 < b1A) || (ob1 == b1A && ok1 < k1A);
            b1A = take ? ob1 : b1A; k1A = take ? ok1 : k1A; b2A = nb2;

            float pb1 = __shfl_xor_sync(0xffffffffu, b1B, off);
            int   pk1 = __shfl_xor_sync(0xffffffffu, k1B, off);
            float pb2 = __shfl_xor_sync(0xffffffffu, b2B, off);
            float qb2 = fminf(fmaxf(b1B, pb1), fminf(b2B, pb2));
            bool tk2 = (pb1 < b1B) || (pb1 == b1B && pk1 < k1B);
            b1B = tk2 ? pb1 : b1B; k1B = tk2 ? pk1 : k1B; b2B = qb2;
        }

        if (gidq == 0) {
            int lr = warp * 16 + grp;
            if (b2A - b1A <= MARGIN) { int qi = atomicAdd(qcnt, 1); queue[qi] = lr; }
            else winners[lr] = k1A;
            int lr2 = lr + 8;
            if (b2B - b1B <= MARGIN) { int qi = atomicAdd(qcnt, 1); queue[qi] = lr2; }
            else winners[lr2] = k1B;
        }
        __syncthreads();

        // ---- exact fp32 rescan for ambiguous rows (rare) ----
        const int nq = *qcnt;
        for (int i = warp; i < nq; i += 16) {
            int lr = queue[i];
            const float* xg = xb + lr;
            float* xs = xscr + warp * 64;
            xs[lane] = xg[(size_t)lane * HW];
            xs[lane + 32] = xg[(size_t)(lane + 32) * HW];
            __syncwarp();
            float best = __int_as_float(0x7f800000);
            int bk = 0;
            #pragma unroll
            for (int j = 0; j < 16; j++) {
                int k = lane + 32 * j;
                float acc = 0.f;
                #pragma unroll
                for (int d = 0; d < EMB_D; d++)
                    acc = fmaf(xs[d], emb_s[d * EMB_K + k], acc);
                float sc = fmaf(-2.f, acc, norms[k]);
                if (sc < best) { best = sc; bk = k; }
            }
            #pragma unroll
            for (int off = 16; off >= 1; off >>= 1) {
                float os = __shfl_xor_sync(0xffffffffu, best, off);
                int   ok = __shfl_xor_sync(0xffffffffu, bk, off);
                bool take = (os < best) || (os == best && ok < bk);
                best = take ? os : best;
                bk = take ? ok : bk;
            }
            if (lane == 0) winners[lr] = bk;
            __syncwarp();
        }
        __syncthreads();

        // ---- outputs ----
        float* oq = out_q + (size_t)b * (EMB_D * HW) + hw_base;
        for (int i = tid; i < TILE_M * EMB_D; i += THREADS) {
            int r = i & (TILE_M - 1);
            int d = i >> 8;
            oq[(size_t)d * HW + r] = emb_s[d * EMB_K + winners[r]];
        }
        if (tid < TILE_M) out_idx[row_base + tid] = (float)winners[tid];
        if (tid == 0) *qcnt = 0;
        __syncthreads();
    }
}

extern "C" void kernel_launch(void* const* d_in, const int* in_sizes, int n_in,
                              void* d_out, int out_size)
{
    const float* x   = (const float*)d_in[0];   // 4194304 f32
    const float* emb = (const float*)d_in[1];   // 32768 f32
    float* out_q = (float*)d_out;
    float* out_i = (float*)d_out + (size_t)4194304;

    cudaFuncSetAttribute(vq_hmma_kernel,
                         cudaFuncAttributeMaxDynamicSharedMemorySize, SM_TOTAL);
    vq_hmma_kernel<<<GRID, THREADS, SM_TOTAL>>>(x, emb, out_q, out_i);
}